// round 13
// baseline (speedup 1.0000x reference)
#include <cuda_runtime.h>
#include <cuda_bf16.h>

// MorletTransform, Goertzel (f32x2), R13: frame split across 2 blocks.
// grid = 2*frames. Block b: frame f=b>>1, half hh=b&1, samples [hh*512,+512).
// 256 threads = 16 quads (4 harmonics each, two f32x2 chains) x 16 segments
// of 32 samples. Rotated per-harmonic partials go to __device__ scratch;
// the LAST-arriving block of each pair finalizes (threadfence + atomic
// counter; deterministic fixed-order sum half0+half1).

#define TWO_PI_F 6.28318530717958647692f
#define MAXF 1024

__device__ float4 g_part[MAXF * 2 * 32];  // [frame][half][lane] = (re0,im0,re1,im1)
__device__ int    g_cnt[MAXF];            // zero-init; reset by finalizer

__device__ __forceinline__ unsigned long long fma2(unsigned long long a,
                                                   unsigned long long b,
                                                   unsigned long long c) {
    unsigned long long d;
    asm("fma.rn.f32x2 %0, %1, %2, %3;" : "=l"(d) : "l"(a), "l"(b), "l"(c));
    return d;
}
__device__ __forceinline__ unsigned long long pk(float lo, float hi) {
    unsigned long long d;
    asm("mov.b64 %0, {%1, %2};" : "=l"(d) : "f"(lo), "f"(hi));
    return d;
}
__device__ __forceinline__ void upk(unsigned long long v, float& lo, float& hi) {
    asm("mov.b64 {%0, %1}, %2;" : "=f"(lo), "=f"(hi) : "l"(v));
}

__global__ void __launch_bounds__(256)
morlet_kernel(const float* __restrict__ audio,
              const float* __restrict__ f0,
              float* __restrict__ out_hd,
              float* __restrict__ out_amp) {
    const int f   = blockIdx.x >> 1;
    const int hh  = blockIdx.x & 1;       // half-frame index
    const int tid = threadIdx.x;
    const int N0  = hh * 512;             // first sample of this half

    __shared__ __align__(16) unsigned long long w2[512];  // (w,w) per sample; 4KB
    __shared__ __align__(16) float2 sPart[16 * 64];       // [seg][harm] y; 8KB
    __shared__ __align__(8)  float sCth[64];
    __shared__ __align__(8)  float sSth[64];
    __shared__ __align__(16) float2 sEb[64];   // e^{-i*2pi*frac((N0+31)fc)}
    __shared__ __align__(16) float2 sE32[64];  // e^{-i*2pi*frac(32 fc)}

    // normalizer = 1/sqrt(pi*tp), tp = sr/half_bw = 16000
    const float normalizer = rsqrtf(3.14159265358979f * 16000.0f);
    const float inv_tp     = 1.0f / 16000.0f;
    const float inv_sr     = 1.0f / 16000.0f;

    // --- GMEM loads up front ---
    float2 a = ((const float2*)audio)[(size_t)f * 512 + hh * 256 + tid];
    const float f0v = f0[f];

    // --- per-harmonic coefficients (overlap the audio load). Recurrence
    //     coeff: accurate sincosf (cos error amplified by ~1/sin(theta)).
    //     Rotation phasors: absolute phases, __sincosf precision ok. ---
    if (tid < 64) {
        float fc = f0v * (float)(tid + 1) * inv_sr;
        float s, c;
        sincosf(TWO_PI_F * fc, &s, &c);
        sCth[tid] = c;
        sSth[tid] = s;
        float pb = fc * (float)(N0 + 31); pb -= floorf(pb);
        float p32 = fc * 32.0f;           p32 -= floorf(p32);
        float sb, cb, s32, c32;
        __sincosf(TWO_PI_F * pb, &sb, &cb);
        __sincosf(TWO_PI_F * p32, &s32, &c32);
        sEb[tid]  = make_float2(cb, -sb);
        sE32[tid] = make_float2(c32, -s32);
    }

    // --- windowed half-frame: thread handles samples N0+2t, N0+2t+1 ---
    {
        int n = N0 + 2 * tid;
        float d0 = (float)(n - 512);
        float d1 = (float)(n + 1 - 512);
        float w0 = a.x * (normalizer * __expf(-d0 * d0 * inv_tp));
        float w1 = a.y * (normalizer * __expf(-d1 * d1 * inv_tp));
        ((ulonglong2*)w2)[tid] = make_ulonglong2(pk(w0, w0), pk(w1, w1));
    }
    __syncthreads();   // barrier #1

    const int quad = tid & 15;   // harmonics 4q+1 .. 4q+4
    const int seg  = tid >> 4;   // 16 segments of 32 samples

    float2 cthP = ((const float2*)sCth)[2 * quad];
    float2 sthP = ((const float2*)sSth)[2 * quad];
    float2 cthQ = ((const float2*)sCth)[2 * quad + 1];
    float2 sthQ = ((const float2*)sSth)[2 * quad + 1];
    const unsigned long long C2P  = pk(2.0f * cthP.x, 2.0f * cthP.y);
    const unsigned long long C2Q  = pk(2.0f * cthQ.x, 2.0f * cthQ.y);
    const unsigned long long NEG1 = pk(-1.0f, -1.0f);

    // --- Goertzel: two f32x2 chains over 32 samples ---
    const ulonglong2* wq = (const ulonglong2*)(w2 + seg * 32);
    unsigned long long p1 = 0ull, p2 = 0ull;
    unsigned long long q1 = 0ull, q2 = 0ull;
    #pragma unroll
    for (int m = 0; m < 16; ++m) {
        ulonglong2 wv = wq[m];
        unsigned long long t0 = fma2(NEG1, p2, wv.x);
        unsigned long long s0 = fma2(C2P, p1, t0);
        unsigned long long u0 = fma2(NEG1, q2, wv.x);
        unsigned long long v0 = fma2(C2Q, q1, u0);
        unsigned long long t1 = fma2(NEG1, p1, wv.y);
        unsigned long long sn = fma2(C2P, s0, t1);
        unsigned long long u1 = fma2(NEG1, q1, wv.y);
        unsigned long long vn = fma2(C2Q, v0, u1);
        p2 = s0; p1 = sn;
        q2 = v0; q1 = vn;
    }

    // --- store UNROTATED y = (s1 - cos*s2, sin*s2) ---
    {
        float x1A, x1B, x2A, x2B;
        upk(p1, x1A, x1B); upk(p2, x2A, x2B);
        sPart[seg * 64 + 4 * quad + 0] =
            make_float2(fmaf(-cthP.x, x2A, x1A), sthP.x * x2A);
        sPart[seg * 64 + 4 * quad + 1] =
            make_float2(fmaf(-cthP.y, x2B, x1B), sthP.y * x2B);
        upk(q1, x1A, x1B); upk(q2, x2A, x2B);
        sPart[seg * 64 + 4 * quad + 2] =
            make_float2(fmaf(-cthQ.x, x2A, x1A), sthQ.x * x2A);
        sPart[seg * 64 + 4 * quad + 3] =
            make_float2(fmaf(-cthQ.y, x2B, x1B), sthQ.y * x2B);
    }
    __syncthreads();   // barrier #2

    // --- single-warp: lane l owns harmonics h = 2l, 2l+1 (0-based).
    //     rot(s) = Eb * E32^s; even/odd phasor chains stepped by E64=E32^2. ---
    if (tid < 32) {
        float4 eb  = *(const float4*)&sEb[2 * tid];
        float4 e32 = *(const float4*)&sE32[2 * tid];
        float e64_0re = fmaf(e32.x, e32.x, -e32.y * e32.y);
        float e64_0im = 2.0f * e32.x * e32.y;
        float e64_1re = fmaf(e32.z, e32.z, -e32.w * e32.w);
        float e64_1im = 2.0f * e32.z * e32.w;
        float ev0re = eb.x, ev0im = eb.y;
        float ev1re = eb.z, ev1im = eb.w;
        float od0re = fmaf(eb.x, e32.x, -eb.y * e32.y);
        float od0im = fmaf(eb.x, e32.y,  eb.y * e32.x);
        float od1re = fmaf(eb.z, e32.z, -eb.w * e32.w);
        float od1im = fmaf(eb.z, e32.w,  eb.w * e32.z);

        float ar0 = 0.0f, ai0 = 0.0f, ar1 = 0.0f, ai1 = 0.0f;
        #pragma unroll
        for (int s = 0; s < 16; s += 2) {
            float4 pq = *(const float4*)&sPart[s * 64 + 2 * tid];
            ar0 = fmaf(pq.x, ev0re, ar0); ar0 = fmaf(-pq.y, ev0im, ar0);
            ai0 = fmaf(pq.x, ev0im, ai0); ai0 = fmaf( pq.y, ev0re, ai0);
            ar1 = fmaf(pq.z, ev1re, ar1); ar1 = fmaf(-pq.w, ev1im, ar1);
            ai1 = fmaf(pq.z, ev1im, ai1); ai1 = fmaf( pq.w, ev1re, ai1);
            float4 pr = *(const float4*)&sPart[(s + 1) * 64 + 2 * tid];
            ar0 = fmaf(pr.x, od0re, ar0); ar0 = fmaf(-pr.y, od0im, ar0);
            ai0 = fmaf(pr.x, od0im, ai0); ai0 = fmaf( pr.y, od0re, ai0);
            ar1 = fmaf(pr.z, od1re, ar1); ar1 = fmaf(-pr.w, od1im, ar1);
            ai1 = fmaf(pr.z, od1im, ai1); ai1 = fmaf( pr.w, od1re, ai1);
            float t;
            t     = fmaf(ev0re, e64_0re, -ev0im * e64_0im);
            ev0im = fmaf(ev0re, e64_0im,  ev0im * e64_0re); ev0re = t;
            t     = fmaf(ev1re, e64_1re, -ev1im * e64_1im);
            ev1im = fmaf(ev1re, e64_1im,  ev1im * e64_1re); ev1re = t;
            t     = fmaf(od0re, e64_0re, -od0im * e64_0im);
            od0im = fmaf(od0re, e64_0im,  od0im * e64_0re); od0re = t;
            t     = fmaf(od1re, e64_1re, -od1im * e64_1im);
            od1im = fmaf(od1re, e64_1im,  od1im * e64_1re); od1re = t;
        }

        // --- publish this half's partials ---
        g_part[(f * 2 + hh) * 32 + tid] = make_float4(ar0, ai0, ar1, ai1);
        __threadfence();

        // --- last-arriving block finalizes (deterministic value) ---
        int old = 0;
        if (tid == 0) old = atomicAdd(&g_cnt[f], 1);
        old = __shfl_sync(0xffffffffu, old, 0);
        if (old == 1) {
            float4 h0 = g_part[(f * 2 + 0) * 32 + tid];
            float4 h1 = g_part[(f * 2 + 1) * 32 + tid];
            float re0 = h0.x + h1.x, im0 = h0.y + h1.y;   // fixed order
            float re1 = h0.z + h1.z, im1 = h0.w + h1.w;
            float mag0 = sqrtf(re0 * re0 + im0 * im0);
            float mag1 = sqrtf(re1 * re1 + im1 * im1);
            float fch0 = f0v * (float)(2 * tid + 1) * inv_sr;
            float fch1 = f0v * (float)(2 * tid + 2) * inv_sr;
            if (fch0 > 0.5f) mag0 = 0.0f;   // Nyquist mask
            if (fch1 > 0.5f) mag1 = 0.0f;

            float s = mag0 + mag1;
            #pragma unroll
            for (int o = 16; o > 0; o >>= 1)
                s += __shfl_xor_sync(0xffffffffu, s, o);

            float inv = 1.0f / s;
            ((float2*)out_hd)[f * 32 + tid] = make_float2(mag0 * inv, mag1 * inv);
            if (tid == 0) {
                out_amp[f] = fminf(fmaxf(s * 2.0f, 0.0f), 1.0f);
                __threadfence();
                g_cnt[f] = 0;              // reset for next (graph) launch
            }
        }
    }
}

extern "C" void kernel_launch(void* const* d_in, const int* in_sizes, int n_in,
                              void* d_out, int out_size) {
    const float* audio = (const float*)d_in[0];
    const float* f0    = (const float*)d_in[1];
    const int frames   = in_sizes[1];  // 2*250*1 = 500
    float* out         = (float*)d_out;
    morlet_kernel<<<frames * 2, 256>>>(audio, f0, out, out + (size_t)frames * 64);
}

// round 14
// speedup vs baseline: 1.1028x; 1.1028x over previous
#include <cuda_runtime.h>
#include <cuda_bf16.h>

// MorletTransform, Goertzel (f32x2 packed). R14: 2 frames per block.
// grid = frames/2, 256 threads. Block b owns frames 2b, 2b+1:
//  - both audio tiles + both f0 loaded at entry (MLP=4)
//  - both coefficient sets computed in parallel (tid<64 / 64..127)
//  - both windows stored to double-buffered w2 before ONE barrier
//  - per frame: quad = tid&15 -> harmonics 4q+1..4q+4 (two f32x2 chains),
//    seg = tid>>4 -> 64-sample segment; trig-free single-warp tail
//    (rot = E63*E64^s, even/odd phasor chains stepped by E128).
//  - frame0's tail (warp 0) overlaps frame1's loop (warps 1-7).

#define TWO_PI_F 6.28318530717958647692f

__device__ __forceinline__ unsigned long long fma2(unsigned long long a,
                                                   unsigned long long b,
                                                   unsigned long long c) {
    unsigned long long d;
    asm("fma.rn.f32x2 %0, %1, %2, %3;" : "=l"(d) : "l"(a), "l"(b), "l"(c));
    return d;
}
__device__ __forceinline__ unsigned long long pk(float lo, float hi) {
    unsigned long long d;
    asm("mov.b64 %0, {%1, %2};" : "=l"(d) : "f"(lo), "f"(hi));
    return d;
}
__device__ __forceinline__ void upk(unsigned long long v, float& lo, float& hi) {
    asm("mov.b64 {%0, %1}, %2;" : "=f"(lo), "=f"(hi) : "l"(v));
}

__global__ void __launch_bounds__(256)
morlet_kernel(const float* __restrict__ audio,
              const float* __restrict__ f0,
              float* __restrict__ out_hd,
              float* __restrict__ out_amp) {
    const int b   = blockIdx.x;
    const int tid = threadIdx.x;

    __shared__ __align__(16) unsigned long long w2[2][1024];  // 16KB
    __shared__ __align__(16) float2 sPart[2][16 * 64];        // 16KB
    __shared__ __align__(8)  float sCth[2][64];
    __shared__ __align__(8)  float sSth[2][64];
    __shared__ __align__(16) float2 sE63[2][64];
    __shared__ __align__(16) float2 sE64[2][64];

    // normalizer = 1/sqrt(pi*tp), tp = sr/half_bw = 16000
    const float normalizer = rsqrtf(3.14159265358979f * 16000.0f);
    const float inv_tp     = 1.0f / 16000.0f;
    const float inv_sr     = 1.0f / 16000.0f;

    // --- all GMEM loads up front (4 independent requests in flight) ---
    float4 a0 = ((const float4*)audio)[(size_t)(2 * b) * 256 + tid];
    float4 a1 = ((const float4*)audio)[(size_t)(2 * b + 1) * 256 + tid];
    const float f0v0 = f0[2 * b];
    const float f0v1 = f0[2 * b + 1];

    // --- both frames' per-harmonic coefficients, in parallel.
    //     Recurrence coeff: accurate sincosf (cos error amplified by
    //     ~1/sin(theta) at small k). E63/E64: absolute phases, __sincosf ok. ---
    if (tid < 128) {
        const int   fi = tid >> 6;
        const int   h  = tid & 63;
        const float fv = fi ? f0v1 : f0v0;
        float fc = fv * (float)(h + 1) * inv_sr;
        float s, c;
        sincosf(TWO_PI_F * fc, &s, &c);
        sCth[fi][h] = c;
        sSth[fi][h] = s;
        float p63 = fc * 63.0f; p63 -= floorf(p63);
        float p64 = fc * 64.0f; p64 -= floorf(p64);
        float s63, c63, s64, c64;
        __sincosf(TWO_PI_F * p63, &s63, &c63);
        __sincosf(TWO_PI_F * p64, &s64, &c64);
        sE63[fi][h] = make_float2(c63, -s63);
        sE64[fi][h] = make_float2(c64, -s64);
    }

    // --- both windowed frames, stored duplicated ---
    {
        int n = tid * 4;
        float g[4];
        #pragma unroll
        for (int i = 0; i < 4; ++i) {
            float d = (float)(n + i - 512);
            g[i] = normalizer * __expf(-d * d * inv_tp);
        }
        ((ulonglong2*)w2[0])[tid * 2] =
            make_ulonglong2(pk(a0.x * g[0], a0.x * g[0]), pk(a0.y * g[1], a0.y * g[1]));
        ((ulonglong2*)w2[0])[tid * 2 + 1] =
            make_ulonglong2(pk(a0.z * g[2], a0.z * g[2]), pk(a0.w * g[3], a0.w * g[3]));
        ((ulonglong2*)w2[1])[tid * 2] =
            make_ulonglong2(pk(a1.x * g[0], a1.x * g[0]), pk(a1.y * g[1], a1.y * g[1]));
        ((ulonglong2*)w2[1])[tid * 2 + 1] =
            make_ulonglong2(pk(a1.z * g[2], a1.z * g[2]), pk(a1.w * g[3], a1.w * g[3]));
    }
    __syncthreads();   // everything staged for both frames

    const int quad = tid & 15;   // harmonics 4q+1 .. 4q+4
    const int seg  = tid >> 4;   // 16 segments of 64 samples

    #pragma unroll
    for (int fi = 0; fi < 2; ++fi) {
        const float f0v = fi ? f0v1 : f0v0;

        float2 cthP = ((const float2*)sCth[fi])[2 * quad];
        float2 sthP = ((const float2*)sSth[fi])[2 * quad];
        float2 cthQ = ((const float2*)sCth[fi])[2 * quad + 1];
        float2 sthQ = ((const float2*)sSth[fi])[2 * quad + 1];
        const unsigned long long C2P  = pk(2.0f * cthP.x, 2.0f * cthP.y);
        const unsigned long long C2Q  = pk(2.0f * cthQ.x, 2.0f * cthQ.y);
        const unsigned long long NEG1 = pk(-1.0f, -1.0f);

        // --- Goertzel: two f32x2 chains over this thread's segment ---
        const ulonglong2* wq = (const ulonglong2*)(w2[fi] + seg * 64);
        unsigned long long p1 = 0ull, p2 = 0ull;
        unsigned long long q1 = 0ull, q2 = 0ull;
        #pragma unroll
        for (int m = 0; m < 32; ++m) {
            ulonglong2 wv = wq[m];
            unsigned long long t0 = fma2(NEG1, p2, wv.x);
            unsigned long long s0 = fma2(C2P, p1, t0);
            unsigned long long u0 = fma2(NEG1, q2, wv.x);
            unsigned long long v0 = fma2(C2Q, q1, u0);
            unsigned long long t1 = fma2(NEG1, p1, wv.y);
            unsigned long long sn = fma2(C2P, s0, t1);
            unsigned long long u1 = fma2(NEG1, q1, wv.y);
            unsigned long long vn = fma2(C2Q, v0, u1);
            p2 = s0; p1 = sn;
            q2 = v0; q1 = vn;
        }

        // --- store UNROTATED y = (s1 - cos*s2, sin*s2) ---
        {
            float x1A, x1B, x2A, x2B;
            upk(p1, x1A, x1B); upk(p2, x2A, x2B);
            sPart[fi][seg * 64 + 4 * quad + 0] =
                make_float2(fmaf(-cthP.x, x2A, x1A), sthP.x * x2A);
            sPart[fi][seg * 64 + 4 * quad + 1] =
                make_float2(fmaf(-cthP.y, x2B, x1B), sthP.y * x2B);
            upk(q1, x1A, x1B); upk(q2, x2A, x2B);
            sPart[fi][seg * 64 + 4 * quad + 2] =
                make_float2(fmaf(-cthQ.x, x2A, x1A), sthQ.x * x2A);
            sPart[fi][seg * 64 + 4 * quad + 3] =
                make_float2(fmaf(-cthQ.y, x2B, x1B), sthQ.y * x2B);
        }
        __syncthreads();   // partials for frame fi visible

        // --- single-warp tail; for fi=0 warps 1-7 proceed to frame 1 loop ---
        if (tid < 32) {
            float4 e63 = *(const float4*)&sE63[fi][2 * tid];
            float4 e64 = *(const float4*)&sE64[fi][2 * tid];
            float e128_0re = fmaf(e64.x, e64.x, -e64.y * e64.y);
            float e128_0im = 2.0f * e64.x * e64.y;
            float e128_1re = fmaf(e64.z, e64.z, -e64.w * e64.w);
            float e128_1im = 2.0f * e64.z * e64.w;
            float ev0re = e63.x, ev0im = e63.y;
            float ev1re = e63.z, ev1im = e63.w;
            float od0re = fmaf(e63.x, e64.x, -e63.y * e64.y);
            float od0im = fmaf(e63.x, e64.y,  e63.y * e64.x);
            float od1re = fmaf(e63.z, e64.z, -e63.w * e64.w);
            float od1im = fmaf(e63.z, e64.w,  e63.w * e64.z);

            float ar0 = 0.0f, ai0 = 0.0f, ar1 = 0.0f, ai1 = 0.0f;
            #pragma unroll
            for (int s = 0; s < 16; s += 2) {
                float4 pq = *(const float4*)&sPart[fi][s * 64 + 2 * tid];
                ar0 = fmaf(pq.x, ev0re, ar0); ar0 = fmaf(-pq.y, ev0im, ar0);
                ai0 = fmaf(pq.x, ev0im, ai0); ai0 = fmaf( pq.y, ev0re, ai0);
                ar1 = fmaf(pq.z, ev1re, ar1); ar1 = fmaf(-pq.w, ev1im, ar1);
                ai1 = fmaf(pq.z, ev1im, ai1); ai1 = fmaf( pq.w, ev1re, ai1);
                float4 pr = *(const float4*)&sPart[fi][(s + 1) * 64 + 2 * tid];
                ar0 = fmaf(pr.x, od0re, ar0); ar0 = fmaf(-pr.y, od0im, ar0);
                ai0 = fmaf(pr.x, od0im, ai0); ai0 = fmaf( pr.y, od0re, ai0);
                ar1 = fmaf(pr.z, od1re, ar1); ar1 = fmaf(-pr.w, od1im, ar1);
                ai1 = fmaf(pr.w, od1re, ai1); ai1 = fmaf( pr.z, od1im, ai1);
                float t;
                t     = fmaf(ev0re, e128_0re, -ev0im * e128_0im);
                ev0im = fmaf(ev0re, e128_0im,  ev0im * e128_0re); ev0re = t;
                t     = fmaf(ev1re, e128_1re, -ev1im * e128_1im);
                ev1im = fmaf(ev1re, e128_1im,  ev1im * e128_1re); ev1re = t;
                t     = fmaf(od0re, e128_0re, -od0im * e128_0im);
                od0im = fmaf(od0re, e128_0im,  od0im * e128_0re); od0re = t;
                t     = fmaf(od1re, e128_1re, -od1im * e128_1im);
                od1im = fmaf(od1re, e128_1im,  od1im * e128_1re); od1re = t;
            }

            float mag0 = sqrtf(ar0 * ar0 + ai0 * ai0);
            float mag1 = sqrtf(ar1 * ar1 + ai1 * ai1);
            float fch0 = f0v * (float)(2 * tid + 1) * inv_sr;
            float fch1 = f0v * (float)(2 * tid + 2) * inv_sr;
            if (fch0 > 0.5f) mag0 = 0.0f;   // Nyquist mask
            if (fch1 > 0.5f) mag1 = 0.0f;

            float s = mag0 + mag1;
            #pragma unroll
            for (int o = 16; o > 0; o >>= 1)
                s += __shfl_xor_sync(0xffffffffu, s, o);

            float inv = 1.0f / s;
            const int fr = 2 * b + fi;
            ((float2*)out_hd)[fr * 32 + tid] = make_float2(mag0 * inv, mag1 * inv);
            if (tid == 0)
                out_amp[fr] = fminf(fmaxf(s * 2.0f, 0.0f), 1.0f);
        }
    }
}

extern "C" void kernel_launch(void* const* d_in, const int* in_sizes, int n_in,
                              void* d_out, int out_size) {
    const float* audio = (const float*)d_in[0];
    const float* f0    = (const float*)d_in[1];
    const int frames   = in_sizes[1];  // 2*250*1 = 500 (even)
    float* out         = (float*)d_out;
    morlet_kernel<<<frames / 2, 256>>>(audio, f0, out, out + (size_t)frames * 64);
}

// round 16
// speedup vs baseline: 1.2421x; 1.1263x over previous
#include <cuda_runtime.h>
#include <cuda_bf16.h>

// MorletTransform via per-harmonic Goertzel recurrence (f32x2 packed lanes).
// Consolidated best config: grid = frames, 256 threads.
// Thread: quad = tid&15 -> harmonics 4q+1..4q+4 as two f32x2 chains (ILP=2);
// seg = tid>>4 -> 64-sample segment. Loop: 1 LDS.128 + 8 FFMA2 / 2 samples.
// Workers store UNROTATED y = (s1 - cos*s2, sin*s2); single-warp tail
// computes its own E63/E64 phasors (4 __sincosf/lane, off the worker path)
// and applies rot = E63*E64^s via even/odd phasor chains (E128 = E64^2).

#define TWO_PI_F 6.28318530717958647692f

__device__ __forceinline__ unsigned long long fma2(unsigned long long a,
                                                   unsigned long long b,
                                                   unsigned long long c) {
    unsigned long long d;
    asm("fma.rn.f32x2 %0, %1, %2, %3;" : "=l"(d) : "l"(a), "l"(b), "l"(c));
    return d;
}
__device__ __forceinline__ unsigned long long pk(float lo, float hi) {
    unsigned long long d;
    asm("mov.b64 %0, {%1, %2};" : "=l"(d) : "f"(lo), "f"(hi));
    return d;
}
__device__ __forceinline__ void upk(unsigned long long v, float& lo, float& hi) {
    asm("mov.b64 {%0, %1}, %2;" : "=f"(lo), "=f"(hi) : "l"(v));
}

__global__ void __launch_bounds__(256)
morlet_kernel(const float* __restrict__ audio,
              const float* __restrict__ f0,
              float* __restrict__ out_hd,
              float* __restrict__ out_amp) {
    const int f   = blockIdx.x;
    const int tid = threadIdx.x;

    __shared__ __align__(16) unsigned long long w2[1024];   // (w[n],w[n]); 8KB
    __shared__ __align__(16) float2 sPart[16 * 64];         // [seg][harm] y; 8KB
    __shared__ __align__(8)  float sCth[64];
    __shared__ __align__(8)  float sSth[64];

    // normalizer = 1/sqrt(pi*tp), tp = sr/half_bw = 16000
    const float normalizer = rsqrtf(3.14159265358979f * 16000.0f);
    const float inv_tp     = 1.0f / 16000.0f;
    const float inv_sr     = 1.0f / 16000.0f;

    // --- issue GMEM loads up front (independent, in flight together) ---
    float4 a = ((const float4*)audio)[(size_t)f * 256 + tid];
    const float f0v = f0[f];

    // --- per-harmonic recurrence coefficients (overlap the audio load).
    //     Accurate sincosf: cos error is amplified by ~N/sin(theta) in the
    //     recurrence (up to ~1e-3 with __sincosf) -> must stay accurate. ---
    if (tid < 64) {
        float fc = f0v * (float)(tid + 1) * inv_sr;
        float s, c;
        sincosf(TWO_PI_F * fc, &s, &c);
        sCth[tid] = c;
        sSth[tid] = s;
    }

    // --- windowed frame: w[n] = audio[n]*normalizer*gauss[n], duplicated ---
    {
        int n = tid * 4;
        float v[4] = {a.x, a.y, a.z, a.w};
        unsigned long long o[4];
        #pragma unroll
        for (int i = 0; i < 4; ++i) {
            float d  = (float)(n + i - 512);
            float wv = v[i] * (normalizer * __expf(-d * d * inv_tp));
            o[i] = pk(wv, wv);
        }
        ((ulonglong2*)w2)[tid * 2]     = make_ulonglong2(o[0], o[1]);
        ((ulonglong2*)w2)[tid * 2 + 1] = make_ulonglong2(o[2], o[3]);
    }
    __syncthreads();   // barrier #1: w2 + coefficients ready

    const int quad = tid & 15;   // harmonics 4q+1 .. 4q+4
    const int seg  = tid >> 4;   // 16 segments of 64 samples

    float2 cthP = ((const float2*)sCth)[2 * quad];       // harmonics 4q+1, 4q+2
    float2 sthP = ((const float2*)sSth)[2 * quad];
    float2 cthQ = ((const float2*)sCth)[2 * quad + 1];   // harmonics 4q+3, 4q+4
    float2 sthQ = ((const float2*)sSth)[2 * quad + 1];
    const unsigned long long C2P  = pk(2.0f * cthP.x, 2.0f * cthP.y);
    const unsigned long long C2Q  = pk(2.0f * cthQ.x, 2.0f * cthQ.y);
    const unsigned long long NEG1 = pk(-1.0f, -1.0f);

    // --- Goertzel: two f32x2 chains over this thread's 64-sample segment ---
    const ulonglong2* wq = (const ulonglong2*)(w2 + seg * 64);

    unsigned long long p1 = 0ull, p2 = 0ull;  // chain P (harmonics 4q+1,4q+2)
    unsigned long long q1 = 0ull, q2 = 0ull;  // chain Q (harmonics 4q+3,4q+4)
    #pragma unroll
    for (int m = 0; m < 32; ++m) {
        ulonglong2 wv = wq[m];                         // 2 samples, duplicated
        unsigned long long t0 = fma2(NEG1, p2, wv.x);  // w - s_{n-2}
        unsigned long long s0 = fma2(C2P, p1, t0);
        unsigned long long u0 = fma2(NEG1, q2, wv.x);
        unsigned long long v0 = fma2(C2Q, q1, u0);
        unsigned long long t1 = fma2(NEG1, p1, wv.y);
        unsigned long long sn = fma2(C2P, s0, t1);
        unsigned long long u1 = fma2(NEG1, q1, wv.y);
        unsigned long long vn = fma2(C2Q, v0, u1);
        p2 = s0; p1 = sn;
        q2 = v0; q1 = vn;
    }

    // --- store UNROTATED y = (s1 - cos*s2, sin*s2) per harmonic (no trig) ---
    {
        float x1A, x1B, x2A, x2B;
        upk(p1, x1A, x1B); upk(p2, x2A, x2B);
        sPart[seg * 64 + 4 * quad + 0] =
            make_float2(fmaf(-cthP.x, x2A, x1A), sthP.x * x2A);
        sPart[seg * 64 + 4 * quad + 1] =
            make_float2(fmaf(-cthP.y, x2B, x1B), sthP.y * x2B);
        upk(q1, x1A, x1B); upk(q2, x2A, x2B);
        sPart[seg * 64 + 4 * quad + 2] =
            make_float2(fmaf(-cthQ.x, x2A, x1A), sthQ.x * x2A);
        sPart[seg * 64 + 4 * quad + 3] =
            make_float2(fmaf(-cthQ.y, x2B, x1B), sthQ.y * x2B);
    }
    __syncthreads();   // barrier #2: partials visible

    // --- single-warp finish: lane l owns harmonics h = 2l, 2l+1.
    //     Phasors E63 = e^{-i*2pi*frac(63 fc)}, E64 = e^{-i*2pi*frac(64 fc)}
    //     computed here (absolute phases -> __sincosf precision suffices).
    //     rot(s) = E63 * E64^s; even/odd chains stepped by E128 = E64^2. ---
    if (tid < 32) {
        float fc0 = f0v * (float)(2 * tid + 1) * inv_sr;
        float fc1 = f0v * (float)(2 * tid + 2) * inv_sr;
        float p, s63, c63, s64, c64;
        p = fc0 * 63.0f; p -= floorf(p);
        __sincosf(TWO_PI_F * p, &s63, &c63);
        p = fc0 * 64.0f; p -= floorf(p);
        __sincosf(TWO_PI_F * p, &s64, &c64);
        float4 e63, e64;
        e63.x = c63; e63.y = -s63;
        e64.x = c64; e64.y = -s64;
        p = fc1 * 63.0f; p -= floorf(p);
        __sincosf(TWO_PI_F * p, &s63, &c63);
        p = fc1 * 64.0f; p -= floorf(p);
        __sincosf(TWO_PI_F * p, &s64, &c64);
        e63.z = c63; e63.w = -s63;
        e64.z = c64; e64.w = -s64;

        float e128_0re = fmaf(e64.x, e64.x, -e64.y * e64.y);
        float e128_0im = 2.0f * e64.x * e64.y;
        float e128_1re = fmaf(e64.z, e64.z, -e64.w * e64.w);
        float e128_1im = 2.0f * e64.z * e64.w;
        float ev0re = e63.x, ev0im = e63.y;
        float ev1re = e63.z, ev1im = e63.w;
        float od0re = fmaf(e63.x, e64.x, -e63.y * e64.y);
        float od0im = fmaf(e63.x, e64.y,  e63.y * e64.x);
        float od1re = fmaf(e63.z, e64.z, -e63.w * e64.w);
        float od1im = fmaf(e63.z, e64.w,  e63.w * e64.z);

        float ar0 = 0.0f, ai0 = 0.0f, ar1 = 0.0f, ai1 = 0.0f;
        #pragma unroll
        for (int s = 0; s < 16; s += 2) {
            float4 pq = *(const float4*)&sPart[s * 64 + 2 * tid];
            ar0 = fmaf(pq.x, ev0re, ar0); ar0 = fmaf(-pq.y, ev0im, ar0);
            ai0 = fmaf(pq.x, ev0im, ai0); ai0 = fmaf( pq.y, ev0re, ai0);
            ar1 = fmaf(pq.z, ev1re, ar1); ar1 = fmaf(-pq.w, ev1im, ar1);
            ai1 = fmaf(pq.z, ev1im, ai1); ai1 = fmaf( pq.w, ev1re, ai1);
            float4 pr = *(const float4*)&sPart[(s + 1) * 64 + 2 * tid];
            ar0 = fmaf(pr.x, od0re, ar0); ar0 = fmaf(-pr.y, od0im, ar0);
            ai0 = fmaf(pr.x, od0im, ai0); ai0 = fmaf( pr.y, od0re, ai0);
            ar1 = fmaf(pr.z, od1re, ar1); ar1 = fmaf(-pr.w, od1im, ar1);
            ai1 = fmaf(pr.z, od1im, ai1); ai1 = fmaf( pr.w, od1re, ai1);
            float t;
            t     = fmaf(ev0re, e128_0re, -ev0im * e128_0im);
            ev0im = fmaf(ev0re, e128_0im,  ev0im * e128_0re); ev0re = t;
            t     = fmaf(ev1re, e128_1re, -ev1im * e128_1im);
            ev1im = fmaf(ev1re, e128_1im,  ev1im * e128_1re); ev1re = t;
            t     = fmaf(od0re, e128_0re, -od0im * e128_0im);
            od0im = fmaf(od0re, e128_0im,  od0im * e128_0re); od0re = t;
            t     = fmaf(od1re, e128_1re, -od1im * e128_1im);
            od1im = fmaf(od1re, e128_1im,  od1im * e128_1re); od1re = t;
        }

        float mag0 = sqrtf(ar0 * ar0 + ai0 * ai0);
        float mag1 = sqrtf(ar1 * ar1 + ai1 * ai1);
        if (fc0 > 0.5f) mag0 = 0.0f;   // Nyquist mask
        if (fc1 > 0.5f) mag1 = 0.0f;

        float s = mag0 + mag1;
        #pragma unroll
        for (int o = 16; o > 0; o >>= 1)
            s += __shfl_xor_sync(0xffffffffu, s, o);   // amp in all lanes

        float inv = 1.0f / s;
        ((float2*)out_hd)[f * 32 + tid] = make_float2(mag0 * inv, mag1 * inv);
        if (tid == 0)
            out_amp[f] = fminf(fmaxf(s * 2.0f, 0.0f), 1.0f);
    }
}

extern "C" void kernel_launch(void* const* d_in, const int* in_sizes, int n_in,
                              void* d_out, int out_size) {
    const float* audio = (const float*)d_in[0];
    const float* f0    = (const float*)d_in[1];
    const int frames   = in_sizes[1];  // 2*250*1 = 500
    float* out         = (float*)d_out;
    morlet_kernel<<<frames, 256>>>(audio, f0, out, out + (size_t)frames * 64);
}